// round 13
// baseline (speedup 1.0000x reference)
#include <cuda_runtime.h>
#include <cuda_fp16.h>
#include <cstdint>

#define N_ITEMS_K 1000000
#define FEAT_K    256
#define BAG_K     128
#define N_BAGS_K  50000
#define TILE_K    256
#define N_TILES_K ((N_ITEMS_K + TILE_K - 1) / TILE_K)   // 3907 (last tile 64 rows)
#define EPS_K     1e-5f

// ---------------- device scratch (statically zero-initialized) ----------------
__device__ float g_scratch[(size_t)N_BAGS_K * BAG_K + 2 * BAG_K];

// ---------------- shared memory layout (byte offsets) ----------------
// seg ids : [0, 1024)
// b vec   : [1024, 1536)
// W fp16  : [2048, 67584)      128 rows x 512 B, K-permuted + XOR swizzle
// x fp16  : [67584, 100352)    2 x (256 rows x 64 B eighth), swizzled
// h fp16  : [100352, 165888)   256 rows x 256 B
#define SM_SEG   0
#define SM_B     1024
#define SM_W     2048
#define SM_X     67584
#define SM_H16   100352
#define SMEM_DYN 165888

__device__ __forceinline__ uint32_t smem_u32(const void* p) {
    uint32_t a;
    asm("{ .reg .u64 t; cvta.to.shared.u64 t, %1; cvt.u32.u64 %0, t; }" : "=r"(a) : "l"(p));
    return a;
}

__device__ __forceinline__ void ldsm4(uint32_t* r, uint32_t addr) {
    asm volatile("ldmatrix.sync.aligned.m8n8.x4.shared.b16 {%0,%1,%2,%3}, [%4];"
                 : "=r"(r[0]), "=r"(r[1]), "=r"(r[2]), "=r"(r[3]) : "r"(addr));
}

__device__ __forceinline__ void mma16816(float* c, uint32_t a0, uint32_t a1,
                                         uint32_t a2, uint32_t a3,
                                         uint32_t b0, uint32_t b1) {
    asm volatile(
        "mma.sync.aligned.m16n8k16.row.col.f32.f16.f16.f32 "
        "{%0,%1,%2,%3},{%4,%5,%6,%7},{%8,%9},{%0,%1,%2,%3};"
        : "+f"(c[0]), "+f"(c[1]), "+f"(c[2]), "+f"(c[3])
        : "r"(a0), "r"(a1), "r"(a2), "r"(a3), "r"(b0), "r"(b1));
}

__global__ void __launch_bounds__(512, 1)
fused_gemm_seg_kernel(const float* __restrict__ x, const float* __restrict__ W,
                      const float* __restrict__ bvec, const int* __restrict__ seg)
{
    extern __shared__ char sm[];
    const uint32_t sb = smem_u32(sm);
    const int tid  = threadIdx.x;
    const int lane = tid & 31;
    const int wid  = tid >> 5;

    int*   seg_s = (int*)(sm + SM_SEG);
    float* b_s   = (float*)(sm + SM_B);

    // ---- staging geometry: thread owns fp32 slot (tid&7) of rows (tid>>3)+64it ----
    const int f4c = tid & 7, row0 = tid >> 3;
    // fp16 store address const: row*64 + ((slot&3 ^ row&3)<<4) + (slot>>2)*8
    const uint32_t sts_c = (uint32_t)SM_X + (uint32_t)row0 * 64u
                         + ((uint32_t)((f4c & 3) ^ (row0 & 3)) << 4)
                         + (uint32_t)(f4c >> 2) * 8u;
    const float4* xf4 = (const float4*)x;
    float4 Lr[4];   // in-flight LDG data for one eighth

    auto issue_ldg = [&](int te, int ee) {
        const int i0 = te * TILE_K;
        #pragma unroll
        for (int it = 0; it < 4; it++) {
            const int r = i0 + row0 + it * 64;
            float4 v = make_float4(0.f, 0.f, 0.f, 0.f);
            if (r < N_ITEMS_K) v = xf4[(size_t)r * 64 + ee * 8 + f4c];
            Lr[it] = v;
        }
    };
    auto cvt_sts = [&](uint32_t bufoff) {
        #pragma unroll
        for (int it = 0; it < 4; it++) {
            __half2 h0 = __float22half2_rn(make_float2(Lr[it].x, Lr[it].y));
            __half2 h1 = __float22half2_rn(make_float2(Lr[it].z, Lr[it].w));
            uint2 u;
            u.x = *(uint32_t*)&h0;
            u.y = *(uint32_t*)&h1;
            *(uint2*)(sm + sts_c + bufoff + (uint32_t)it * 4096u) = u;
        }
    };

    // prologue LDG of eighth 0 first (latency hidden under W staging)
    issue_ldg(blockIdx.x, 0);

    // ---- one-time: W -> fp16, K-permuted within each 16-group, swizzled ----
    for (int idx = tid; idx < BAG_K * FEAT_K; idx += 512) {
        int n = idx >> 8, k = idx & 255;
        int s = k >> 4, r = k & 15, tq = r >> 2, j = r & 3;
        int p = (j < 2) ? (2 * tq + j) : (8 + 2 * tq + (j - 2));
        int ks = 16 * s + p;
        uint32_t off = (uint32_t)n * 512u
                     + ((uint32_t)((ks >> 3) ^ (n & 7)) << 4)
                     + (uint32_t)(ks & 7) * 2u;
        *(__half*)(sm + SM_W + off) = __float2half_rn(W[idx]);
    }
    if (tid < BAG_K) b_s[tid] = bvec[tid];

    // warp tiling: 8 M-groups (32 rows each) x 2 N-halves (64 cols)
    const int mgrp = wid >> 1;
    const int nq   = wid & 1;

    // fragment lane geometry
    const int g  = lane >> 2;
    const int tq = lane & 3;
    const int b_ln = ((lane >> 4) << 3) + (lane & 7);
    const int b_ku = (lane >> 3) & 1;
    const int lane7 = lane & 7;
    const int R = mgrp * 32 + g;

    const uint32_t kb = (uint32_t)(b_ku ^ (lane7 & 1)) << 4;
    const uint32_t l6 = (uint32_t)(lane7 & 6);
    uint32_t Bb[4];
    #pragma unroll
    for (int j = 0; j < 4; j++)
        Bb[j] = sb + SM_W + (uint32_t)(nq * 64 + b_ln) * 512u + (uint32_t)j * 8192u + kb;
    // fp16 A addresses: row-slice i at (R+8i)*64 + ((tq ^ (g&3))<<4)
    uint32_t Ax[4];
    #pragma unroll
    for (int i = 0; i < 4; i++)
        Ax[i] = (uint32_t)SM_X + (uint32_t)(R + 8 * i) * 64u
              + ((uint32_t)(tq ^ (g & 3)) << 4);

    // finish prologue: e0 -> buf0, LDG e1
    cvt_sts(0u);
    issue_ldg(blockIdx.x, 1);

    for (int t = blockIdx.x; t < N_TILES_K; t += gridDim.x) {
        const int i0 = t * TILE_K;
        const int rows = min(TILE_K, N_ITEMS_K - i0);
        const int tn = t + gridDim.x;
        const int tnc = (tn < N_TILES_K) ? tn : t;   // clamped: redundant, unread
        int segreg = 0;
        if (tid < rows) segreg = seg[i0 + tid];

        float acc[2][8][4];
        #pragma unroll
        for (int m = 0; m < 2; m++)
            #pragma unroll
            for (int n = 0; n < 8; n++)
                #pragma unroll
                for (int i = 0; i < 4; i++) acc[m][n][i] = 0.f;

        #pragma unroll
        for (int e = 0; e < 8; e++) {
            __syncthreads();   // (e)'s STS visible; buf[(e+1)&1] readers done
            const uint32_t bo = (uint32_t)(e & 1) * 16384u;

            // A fragments for BOTH k-steps of this eighth (one LDS.128/slice)
            uint4 LA0 = *(const uint4*)(sm + Ax[0] + bo);
            uint4 LA1 = *(const uint4*)(sm + Ax[1] + bo);
            uint4 LA2 = *(const uint4*)(sm + Ax[2] + bo);
            uint4 LA3 = *(const uint4*)(sm + Ax[3] + bo);

            // stream: store eighth e+1, load eighth e+2
            cvt_sts((uint32_t)((e + 1) & 1) * 16384u);
            {
                int te = t, ee = e + 2;
                if (ee >= 8) { te = tnc; ee -= 8; }
                issue_ldg(te, ee);
            }

            #pragma unroll
            for (int sl = 0; sl < 2; sl++) {
                const uint32_t offB = ((uint32_t)(4 * e + 2 * sl) ^ l6) << 4;
                uint32_t B[4][4];
                ldsm4(B[0], Bb[0] + offB);
                ldsm4(B[1], Bb[1] + offB);
                ldsm4(B[2], Bb[2] + offB);
                ldsm4(B[3], Bb[3] + offB);

                const uint32_t a00 = sl ? LA0.z : LA0.x;
                const uint32_t a01 = sl ? LA1.z : LA1.x;
                const uint32_t a02 = sl ? LA0.w : LA0.y;
                const uint32_t a03 = sl ? LA1.w : LA1.y;
                const uint32_t a10 = sl ? LA2.z : LA2.x;
                const uint32_t a11 = sl ? LA3.z : LA3.x;
                const uint32_t a12 = sl ? LA2.w : LA2.y;
                const uint32_t a13 = sl ? LA3.w : LA3.y;

                #pragma unroll
                for (int j = 0; j < 4; j++) {
                    mma16816(acc[0][2*j],   a00, a01, a02, a03, B[j][0], B[j][1]);
                    mma16816(acc[0][2*j+1], a00, a01, a02, a03, B[j][2], B[j][3]);
                }
                #pragma unroll
                for (int j = 0; j < 4; j++) {
                    mma16816(acc[1][2*j],   a10, a11, a12, a13, B[j][0], B[j][1]);
                    mma16816(acc[1][2*j+1], a10, a11, a12, a13, B[j][2], B[j][3]);
                }
            }
        }

        // ---- epilogue: +b, relu, h fp16 (dedicated region) ----
        {
            const int c0 = nq * 64 + 2 * tq;
            #pragma unroll
            for (int m = 0; m < 2; m++) {
                char* base0 = sm + SM_H16 + (size_t)(R + 16 * m) * 256;
                char* base1 = base0 + 8 * 256;
                #pragma unroll
                for (int n = 0; n < 8; n++) {
                    const int c = c0 + n * 8;
                    const uint32_t so = ((uint32_t)((nq * 8 + n) ^ g) << 4)
                                      + (uint32_t)tq * 4u;
                    const float b0 = b_s[c], b1 = b_s[c + 1];
                    __half2 u0 = __float22half2_rn(make_float2(
                        fmaxf(acc[m][n][0] + b0, 0.f), fmaxf(acc[m][n][1] + b1, 0.f)));
                    __half2 u1 = __float22half2_rn(make_float2(
                        fmaxf(acc[m][n][2] + b0, 0.f), fmaxf(acc[m][n][3] + b1, 0.f)));
                    *(__half2*)(base0 + so) = u0;
                    *(__half2*)(base1 + so) = u1;
                }
            }
        }
        if (tid < rows) seg_s[tid] = segreg;
        __syncthreads();

        // ---- segment reduce: 8 row-groups (32 rows) x 64 col-pairs (half2) ----
        {
            const int cp   = tid & 63;           // column pair: cols 2cp, 2cp+1
            const int r0   = (tid >> 6) * 32;
            const int rend = min(rows, r0 + 32);
            const uint32_t slot = (uint32_t)(cp >> 2);
            const uint32_t intra = (uint32_t)(cp & 3) * 4u;
            if (r0 < rows) {
                float a0 = 0.f, a1 = 0.f;
                int cur = seg_s[r0];
                const int c = 2 * cp;
                for (int r = r0; r < rend; r++) {
                    int s = seg_s[r];
                    if (s != cur) {
                        atomicAdd(&g_scratch[(size_t)cur * BAG_K + c], a0);
                        atomicAdd(&g_scratch[(size_t)cur * BAG_K + c + 1], a1);
                        a0 = 0.f; a1 = 0.f;
                        cur = s;
                    }
                    __half2 hv = *(const __half2*)(sm + SM_H16 + (size_t)r * 256
                               + (((slot ^ (uint32_t)(r & 7)) << 4) + intra));
                    float2 fv = __half22float2(hv);
                    a0 += fv.x; a1 += fv.y;
                }
                atomicAdd(&g_scratch[(size_t)cur * BAG_K + c], a0);
                atomicAdd(&g_scratch[(size_t)cur * BAG_K + c + 1], a1);
            }
        }
        // no trailing sync: next tile's eighth-syncs order everything; the h
        // region is written again only after 8 more barriers.
    }
}

// ---- per-column batch stats over the 50k bag means (vectorized) ----
__global__ void __launch_bounds__(256) stats_kernel(const int* __restrict__ blen)
{
    __shared__ float4 red_s[8][32];
    __shared__ float4 red_ss[8][32];
    const int c4 = threadIdx.x & 31;
    const int rs = threadIdx.x >> 5;
    float4 s  = make_float4(0.f, 0.f, 0.f, 0.f);
    float4 ss = make_float4(0.f, 0.f, 0.f, 0.f);
    const float4* gs = (const float4*)g_scratch;
    for (int r = blockIdx.x * 8 + rs; r < N_BAGS_K; r += gridDim.x * 8) {
        float inv = 1.f / (float)max(blen[r], 1);
        float4 v = gs[(size_t)r * 32 + c4];
        v.x *= inv; v.y *= inv; v.z *= inv; v.w *= inv;
        s.x += v.x;  s.y += v.y;  s.z += v.z;  s.w += v.w;
        ss.x += v.x * v.x; ss.y += v.y * v.y; ss.z += v.z * v.z; ss.w += v.w * v.w;
    }
    red_s[rs][c4]  = s;
    red_ss[rs][c4] = ss;
    __syncthreads();
    if (rs == 0) {
        #pragma unroll
        for (int i = 1; i < 8; i++) {
            float4 a = red_s[i][c4], b = red_ss[i][c4];
            s.x += a.x; s.y += a.y; s.z += a.z; s.w += a.w;
            ss.x += b.x; ss.y += b.y; ss.z += b.z; ss.w += b.w;
        }
        float* dst  = &g_scratch[(size_t)N_BAGS_K * BAG_K + c4 * 4];
        float* dst2 = &g_scratch[(size_t)N_BAGS_K * BAG_K + BAG_K + c4 * 4];
        atomicAdd(dst + 0, s.x);  atomicAdd(dst + 1, s.y);
        atomicAdd(dst + 2, s.z);  atomicAdd(dst + 3, s.w);
        atomicAdd(dst2 + 0, ss.x); atomicAdd(dst2 + 1, ss.y);
        atomicAdd(dst2 + 2, ss.z); atomicAdd(dst2 + 3, ss.w);
    }
}

// ---- normalize; also restores segment-sum scratch to zero for next launch ----
__global__ void __launch_bounds__(256) norm_kernel(const int* __restrict__ blen,
                                                   const float* __restrict__ gamma,
                                                   const float* __restrict__ beta,
                                                   float* __restrict__ out)
{
    const int c4 = threadIdx.x & 31;
    const int rs = threadIdx.x >> 5;
    const float inv_n = 1.f / (float)N_BAGS_K;
    float4 m = *(const float4*)&g_scratch[(size_t)N_BAGS_K * BAG_K + c4 * 4];
    float4 e = *(const float4*)&g_scratch[(size_t)N_BAGS_K * BAG_K + BAG_K + c4 * 4];
    float4 ga = ((const float4*)gamma)[c4];
    float4 be = ((const float4*)beta)[c4];
    float4 mean, scale;
    mean.x = m.x * inv_n; mean.y = m.y * inv_n;
    mean.z = m.z * inv_n; mean.w = m.w * inv_n;
    scale.x = rsqrtf(e.x * inv_n - mean.x * mean.x + EPS_K) * ga.x;
    scale.y = rsqrtf(e.y * inv_n - mean.y * mean.y + EPS_K) * ga.y;
    scale.z = rsqrtf(e.z * inv_n - mean.z * mean.z + EPS_K) * ga.z;
    scale.w = rsqrtf(e.w * inv_n - mean.w * mean.w + EPS_K) * ga.w;
    float4* gs = (float4*)g_scratch;
    float4* o4 = (float4*)out;
    const float4 z4 = make_float4(0.f, 0.f, 0.f, 0.f);
    for (int r = blockIdx.x * 8 + rs; r < N_BAGS_K; r += gridDim.x * 8) {
        float inv = 1.f / (float)max(blen[r], 1);
        float4 v = gs[(size_t)r * 32 + c4];
        float4 o;
        o.x = (v.x * inv - mean.x) * scale.x + be.x;
        o.y = (v.y * inv - mean.y) * scale.y + be.y;
        o.z = (v.z * inv - mean.z) * scale.z + be.z;
        o.w = (v.w * inv - mean.w) * scale.w + be.w;
        o4[(size_t)r * 32 + c4] = o;
        gs[(size_t)r * 32 + c4] = z4;   // restore zeros for next launch/replay
    }
}

extern "C" void kernel_launch(void* const* d_in, const int* in_sizes, int n_in,
                              void* d_out, int out_size)
{
    const float* x     = (const float*)d_in[0];
    const float* W     = (const float*)d_in[1];
    const float* bvec  = (const float*)d_in[2];
    const float* gamma = (const float*)d_in[3];
    const float* beta  = (const float*)d_in[4];
    const int*   seg   = (const int*)d_in[5];
    const int*   blen  = (const int*)d_in[6];
    float*       out   = (float*)d_out;

    (void)in_sizes; (void)n_in; (void)out_size;

    void* scratch = nullptr;
    cudaGetSymbolAddress(&scratch, g_scratch);
    cudaMemsetAsync((char*)scratch + sizeof(float) * (size_t)N_BAGS_K * BAG_K, 0,
                    sizeof(float) * 2 * BAG_K, 0);

    int dev = 0, nsm = 148;
    cudaGetDevice(&dev);
    cudaDeviceGetAttribute(&nsm, cudaDevAttrMultiProcessorCount, dev);

    cudaFuncSetAttribute(fused_gemm_seg_kernel,
                         cudaFuncAttributeMaxDynamicSharedMemorySize, SMEM_DYN);
    fused_gemm_seg_kernel<<<nsm, 512, SMEM_DYN>>>(x, W, bvec, seg);
    stats_kernel<<<256, 256>>>(blen);
    norm_kernel<<<1024, 256>>>(blen, gamma, beta, out);
}

// round 14
// speedup vs baseline: 1.5432x; 1.5432x over previous
#include <cuda_runtime.h>
#include <cuda_fp16.h>
#include <cstdint>

#define N_ITEMS_K 1000000
#define FEAT_K    256
#define BAG_K     128
#define N_BAGS_K  50000
#define TILE_K    256
#define N_TILES_K ((N_ITEMS_K + TILE_K - 1) / TILE_K)   // 3907 (last tile 64 rows)
#define EPS_K     1e-5f

// ---------------- device scratch (statically zero-initialized) ----------------
__device__ float g_scratch[(size_t)N_BAGS_K * BAG_K + 2 * BAG_K];

// ---------------- shared memory layout (byte offsets) ----------------
// seg     : [0, 1024)       8 pairs x 32 ints
// b vec   : [1024, 1536)
// W fp16  : [2048, 67584)   128 rows x 512 B, K-permuted + XOR swizzle
// x fp32  : [67584, 165888) 8 pairs x 3 bufs x 4096 B (32 rows x 128 B eighth)
// h fp16  : [165888, 231424) 8 pairs x 8192 B (32 rows x 256 B)
#define SM_SEG   0
#define SM_B     1024
#define SM_W     2048
#define SM_X     67584
#define SM_H16   165888
#define SMEM_DYN 231424

__device__ __forceinline__ uint32_t smem_u32(const void* p) {
    uint32_t a;
    asm("{ .reg .u64 t; cvta.to.shared.u64 t, %1; cvt.u32.u64 %0, t; }" : "=r"(a) : "l"(p));
    return a;
}

__device__ __forceinline__ void ldsm4(uint32_t* r, uint32_t addr) {
    asm volatile("ldmatrix.sync.aligned.m8n8.x4.shared.b16 {%0,%1,%2,%3}, [%4];"
                 : "=r"(r[0]), "=r"(r[1]), "=r"(r[2]), "=r"(r[3]) : "r"(addr));
}

__device__ __forceinline__ void mma16816(float* c, const uint32_t* a,
                                         uint32_t b0, uint32_t b1) {
    asm volatile(
        "mma.sync.aligned.m16n8k16.row.col.f32.f16.f16.f32 "
        "{%0,%1,%2,%3},{%4,%5,%6,%7},{%8,%9},{%0,%1,%2,%3};"
        : "+f"(c[0]), "+f"(c[1]), "+f"(c[2]), "+f"(c[3])
        : "r"(a[0]), "r"(a[1]), "r"(a[2]), "r"(a[3]), "r"(b0), "r"(b1));
}

__device__ __forceinline__ void cp_async16z(uint32_t dst, const void* src, bool pred) {
    int sz = pred ? 16 : 0;
    asm volatile("cp.async.cg.shared.global [%0], [%1], 16, %2;"
                 :: "r"(dst), "l"(src), "r"(sz) : "memory");
}
#define CP_COMMIT() asm volatile("cp.async.commit_group;" ::: "memory")
#define CP_WAIT1()  asm volatile("cp.async.wait_group 1;" ::: "memory")
#define CP_WAIT0()  asm volatile("cp.async.wait_group 0;" ::: "memory")

// pair-scope named barrier (64 threads, id = pair index 0..7)
#define BARP(id) asm volatile("bar.sync %0, 64;" :: "r"(id) : "memory")

// staging swizzle: 8-lane store/load phases hit 8 distinct 16B slots
__device__ __forceinline__ int swz(int r) {
    return ((r & 1) << 2) | ((r >> 1) & 3);
}

__global__ void __launch_bounds__(512, 1)
fused_gemm_seg_kernel(const float* __restrict__ x, const float* __restrict__ W,
                      const float* __restrict__ bvec, const int* __restrict__ seg)
{
    extern __shared__ char sm[];
    const uint32_t sb = smem_u32(sm);
    const int tid  = threadIdx.x;
    const int lane = tid & 31;
    const int wid  = tid >> 5;

    int*   seg_s = (int*)(sm + SM_SEG);
    float* b_s   = (float*)(sm + SM_B);

    // warp-pair tiling: pair = mgrp (32 rows), member nq (64 cols)
    const int mgrp = wid >> 1;
    const int nq   = wid & 1;

    // fragment lane geometry
    const int g  = lane >> 2;
    const int tq = lane & 3;
    const int b_ln = ((lane >> 4) << 3) + (lane & 7);
    const int b_ku = (lane >> 3) & 1;
    const int lane7 = lane & 7;

    const uint32_t pairx = (uint32_t)SM_X + (uint32_t)mgrp * 12288u;
    const uint32_t pairh = (uint32_t)SM_H16 + (uint32_t)mgrp * 8192u;

    // B addresses (W layout identical to R11/R12)
    const uint32_t kb = (uint32_t)(b_ku ^ (lane7 & 1)) << 4;
    const uint32_t l6 = (uint32_t)(lane7 & 6);
    uint32_t Bb[4];
    #pragma unroll
    for (int j = 0; j < 4; j++)
        Bb[j] = sb + SM_W + (uint32_t)(nq * 64 + b_ln) * 512u + (uint32_t)j * 8192u + kb;

    // A addresses (pair-local rows g, g+8, g+16, g+24)
    uint32_t Ai[4];
    #pragma unroll
    for (int i = 0; i < 4; i++)
        Ai[i] = (uint32_t)(g + 8 * i) * 128u;
    const uint32_t offA0 = (uint32_t)((0 + tq) ^ swz(g)) << 4;   // sl=0
    const uint32_t offA1 = (uint32_t)((4 + tq) ^ swz(g)) << 4;   // sl=1

    // staging geometry (nq0 warp): iteration it covers rows it*4 + (lane>>3)
    const int srw = lane >> 3, sf4 = lane & 7;
    const float4* xf4 = (const float4*)x;

    auto issue_e = [&](int te, int ee, uint32_t bufoff) {
        const int gb = te * TILE_K + mgrp * 32;
        #pragma unroll
        for (int it = 0; it < 8; it++) {
            const int rp = it * 4 + srw;
            cp_async16z(sb + bufoff + (uint32_t)rp * 128u
                            + ((uint32_t)(sf4 ^ swz(rp)) << 4),
                        xf4 + (size_t)(gb + rp) * 64 + ee * 8 + sf4,
                        gb + rp < N_ITEMS_K);
        }
    };

    // prologue: first tile's eighths 0,1 (issued before W staging to hide)
    if (nq == 0) {
        issue_e(blockIdx.x, 0, pairx);          CP_COMMIT();
        issue_e(blockIdx.x, 1, pairx + 4096u);  CP_COMMIT();
    }

    // ---- one-time: W -> fp16, K-permuted within each 16-group, swizzled ----
    for (int idx = tid; idx < BAG_K * FEAT_K; idx += 512) {
        int n = idx >> 8, k = idx & 255;
        int s = k >> 4, r = k & 15, tqw = r >> 2, j = r & 3;
        int p = (j < 2) ? (2 * tqw + j) : (8 + 2 * tqw + (j - 2));
        int ks = 16 * s + p;
        uint32_t off = (uint32_t)n * 512u
                     + ((uint32_t)((ks >> 3) ^ (n & 7)) << 4)
                     + (uint32_t)(ks & 7) * 2u;
        *(__half*)(sm + SM_W + off) = __float2half_rn(W[idx]);
    }
    if (tid < BAG_K) b_s[tid] = bvec[tid];
    __syncthreads();   // only block-wide sync: W/b staged

    uint32_t rot = 0;
    for (int t = blockIdx.x; t < N_TILES_K; t += gridDim.x) {
        const int i0 = t * TILE_K;
        const int tn = t + gridDim.x;
        const int tnc = (tn < N_TILES_K) ? tn : t;   // clamped: redundant, unread

        // pair's 3 buffer offsets for e%3 = 0,1,2
        uint32_t bb[3];
        bb[0] = pairx + rot * 4096u;
        bb[1] = pairx + ((rot == 2) ? 0u : (rot + 1) * 4096u);
        bb[2] = pairx + ((rot == 0) ? 8192u : (rot - 1) * 4096u);

        // preload this pair's seg ids (stored to smem after epilogue)
        int sv = 0;
        const int gseg = i0 + mgrp * 32 + lane;
        if (nq == 0 && gseg < N_ITEMS_K) sv = seg[gseg];

        float acc[2][8][4];
        #pragma unroll
        for (int m = 0; m < 2; m++)
            #pragma unroll
            for (int n = 0; n < 8; n++)
                #pragma unroll
                for (int i = 0; i < 4; i++) acc[m][n][i] = 0.f;

        #pragma unroll
        for (int e = 0; e < 8; e++) {
            if (nq == 0) CP_WAIT1();
            BARP(mgrp);                    // e visible; buf[(e+2)%3] free
            if (nq == 0) {                 // refill freed buffer with e+2
                int te = t, ee = e + 2;
                if (ee >= 8) { te = tnc; ee -= 8; }
                issue_e(te, ee, bb[(e + 2) % 3]);
                CP_COMMIT();
            }
            const uint32_t bo = bb[e % 3];

            #pragma unroll
            for (int sl = 0; sl < 2; sl++) {
                const uint32_t offB = ((uint32_t)(4 * e + 2 * sl) ^ l6) << 4;
                uint32_t B[4][4];
                ldsm4(B[0], Bb[0] + offB);
                ldsm4(B[1], Bb[1] + offB);
                ldsm4(B[2], Bb[2] + offB);
                ldsm4(B[3], Bb[3] + offB);
                const uint32_t oa = (sl ? offA1 : offA0) + bo;
                float4 v0 = *(const float4*)(sm + Ai[0] + oa);
                float4 v1 = *(const float4*)(sm + Ai[1] + oa);
                float4 v2 = *(const float4*)(sm + Ai[2] + oa);
                float4 v3 = *(const float4*)(sm + Ai[3] + oa);

                uint32_t Ah[4];
                {
                    __half2 h0 = __float22half2_rn(make_float2(v0.x, v0.y));
                    __half2 h1 = __float22half2_rn(make_float2(v1.x, v1.y));
                    __half2 h2 = __float22half2_rn(make_float2(v0.z, v0.w));
                    __half2 h3 = __float22half2_rn(make_float2(v1.z, v1.w));
                    Ah[0] = *(uint32_t*)&h0; Ah[1] = *(uint32_t*)&h1;
                    Ah[2] = *(uint32_t*)&h2; Ah[3] = *(uint32_t*)&h3;
                }
                #pragma unroll
                for (int j = 0; j < 4; j++) {
                    mma16816(acc[0][2*j],   Ah, B[j][0], B[j][1]);
                    mma16816(acc[0][2*j+1], Ah, B[j][2], B[j][3]);
                }
                {
                    __half2 h0 = __float22half2_rn(make_float2(v2.x, v2.y));
                    __half2 h1 = __float22half2_rn(make_float2(v3.x, v3.y));
                    __half2 h2 = __float22half2_rn(make_float2(v2.z, v2.w));
                    __half2 h3 = __float22half2_rn(make_float2(v3.z, v3.w));
                    Ah[0] = *(uint32_t*)&h0; Ah[1] = *(uint32_t*)&h1;
                    Ah[2] = *(uint32_t*)&h2; Ah[3] = *(uint32_t*)&h3;
                }
                #pragma unroll
                for (int j = 0; j < 4; j++) {
                    mma16816(acc[1][2*j],   Ah, B[j][0], B[j][1]);
                    mma16816(acc[1][2*j+1], Ah, B[j][2], B[j][3]);
                }
            }
        }

        // ---- epilogue: +b, relu, h fp16 into pair region ----
        {
            const int c0 = nq * 64 + 2 * tq;
            #pragma unroll
            for (int m = 0; m < 2; m++) {
                char* base0 = sm + pairh + (size_t)(g + 16 * m) * 256;
                char* base1 = base0 + 8 * 256;
                #pragma unroll
                for (int n = 0; n < 8; n++) {
                    const int c = c0 + n * 8;
                    const uint32_t so = ((uint32_t)((nq * 8 + n) ^ g) << 4)
                                      + (uint32_t)tq * 4u;
                    const float b0 = b_s[c], b1 = b_s[c + 1];
                    __half2 u0 = __float22half2_rn(make_float2(
                        fmaxf(acc[m][n][0] + b0, 0.f), fmaxf(acc[m][n][1] + b1, 0.f)));
                    __half2 u1 = __float22half2_rn(make_float2(
                        fmaxf(acc[m][n][2] + b0, 0.f), fmaxf(acc[m][n][3] + b1, 0.f)));
                    *(__half2*)(base0 + so) = u0;
                    *(__half2*)(base1 + so) = u1;
                }
            }
        }
        if (nq == 0) seg_s[mgrp * 32 + lane] = sv;
        BARP(mgrp);    // h + seg visible to both pair warps

        // ---- segment reduce: pair-local, 64 threads x 64 col-pairs ----
        {
            const int gb = i0 + mgrp * 32;
            if (gb < N_ITEMS_K) {
                const int rend = min(32, N_ITEMS_K - gb);
                const int cp = nq * 32 + lane;     // col pair 0..63
                const uint32_t cb = (uint32_t)(cp >> 2);
                const uint32_t intra = (uint32_t)(cp & 3) * 4u;
                const int c = 2 * cp;
                float a0 = 0.f, a1 = 0.f;
                int cur = seg_s[mgrp * 32];
                for (int r = 0; r < rend; r++) {
                    int s = seg_s[mgrp * 32 + r];
                    if (s != cur) {
                        atomicAdd(&g_scratch[(size_t)cur * BAG_K + c], a0);
                        atomicAdd(&g_scratch[(size_t)cur * BAG_K + c + 1], a1);
                        a0 = 0.f; a1 = 0.f;
                        cur = s;
                    }
                    __half2 hv = *(const __half2*)(sm + pairh + (size_t)r * 256
                               + (((cb ^ (uint32_t)(r & 7)) << 4) + intra));
                    float2 fv = __half22float2(hv);
                    a0 += fv.x; a1 += fv.y;
                }
                atomicAdd(&g_scratch[(size_t)cur * BAG_K + c], a0);
                atomicAdd(&g_scratch[(size_t)cur * BAG_K + c + 1], a1);
            }
        }
        // no trailing barrier: next tile's first BARP orders reduce vs reuse
        rot = (rot + 2) % 3;   // 8 eighths -> rotation advances by 8 % 3
    }
    if (nq == 0) CP_WAIT0();   // drain before smem release
}

// ---- per-column batch stats over the 50k bag means (vectorized) ----
__global__ void __launch_bounds__(256) stats_kernel(const int* __restrict__ blen)
{
    __shared__ float4 red_s[8][32];
    __shared__ float4 red_ss[8][32];
    const int c4 = threadIdx.x & 31;
    const int rs = threadIdx.x >> 5;
    float4 s  = make_float4(0.f, 0.f, 0.f, 0.f);
    float4 ss = make_float4(0.f, 0.f, 0.f, 0.f);
    const float4* gs = (const float4*)g_scratch;
    for (int r = blockIdx.x * 8 + rs; r < N_BAGS_K; r += gridDim.x * 8) {
        float inv = 1.f / (float)max(blen[r], 1);
        float4 v = gs[(size_t)r * 32 + c4];
        v.x *= inv; v.y *= inv; v.z *= inv; v.w *= inv;
        s.x += v.x;  s.y += v.y;  s.z += v.z;  s.w += v.w;
        ss.x += v.x * v.x; ss.y += v.y * v.y; ss.z += v.z * v.z; ss.w += v.w * v.w;
    }
    red_s[rs][c4]  = s;
    red_ss[rs][c4] = ss;
    __syncthreads();
    if (rs == 0) {
        #pragma unroll
        for (int i = 1; i < 8; i++) {
            float4 a = red_s[i][c4], b = red_ss[i][c4];
            s.x += a.x; s.y += a.y; s.z += a.z; s.w += a.w;
            ss.x += b.x; ss.y += b.y; ss.z += b.z; ss.w += b.w;
        }
        float* dst  = &g_scratch[(size_t)N_BAGS_K * BAG_K + c4 * 4];
        float* dst2 = &g_scratch[(size_t)N_BAGS_K * BAG_K + BAG_K + c4 * 4];
        atomicAdd(dst + 0, s.x);  atomicAdd(dst + 1, s.y);
        atomicAdd(dst + 2, s.z);  atomicAdd(dst + 3, s.w);
        atomicAdd(dst2 + 0, ss.x); atomicAdd(dst2 + 1, ss.y);
        atomicAdd(dst2 + 2, ss.z); atomicAdd(dst2 + 3, ss.w);
    }
}

// ---- normalize; restores segment-sum scratch to zero for next launch ----
__global__ void __launch_bounds__(256) norm_kernel(const int* __restrict__ blen,
                                                   const float* __restrict__ gamma,
                                                   const float* __restrict__ beta,
                                                   float* __restrict__ out)
{
    const int c4 = threadIdx.x & 31;
    const int rs = threadIdx.x >> 5;
    const float inv_n = 1.f / (float)N_BAGS_K;
    float4 m = *(const float4*)&g_scratch[(size_t)N_BAGS_K * BAG_K + c4 * 4];
    float4 e = *(const float4*)&g_scratch[(size_t)N_BAGS_K * BAG_K + BAG_K + c4 * 4];
    float4 ga = ((const float4*)gamma)[c4];
    float4 be = ((const float4*)beta)[c4];
    float4 mean, scale;
    mean.x = m.x * inv_n; mean.y = m.y * inv_n;
    mean.z = m.z * inv_n; mean.w = m.w * inv_n;
    scale.x = rsqrtf(e.x * inv_n - mean.x * mean.x + EPS_K) * ga.x;
    scale.y = rsqrtf(e.y * inv_n - mean.y * mean.y + EPS_K) * ga.y;
    scale.z = rsqrtf(e.z * inv_n - mean.z * mean.z + EPS_K) * ga.z;
    scale.w = rsqrtf(e.w * inv_n - mean.w * mean.w + EPS_K) * ga.w;
    float4* gs = (float4*)g_scratch;
    float4* o4 = (float4*)out;
    const float4 z4 = make_float4(0.f, 0.f, 0.f, 0.f);
    for (int r = blockIdx.x * 8 + rs; r < N_BAGS_K; r += gridDim.x * 8) {
        float inv = 1.f / (float)max(blen[r], 1);
        float4 v = gs[(size_t)r * 32 + c4];
        float4 o;
        o.x = (v.x * inv - mean.x) * scale.x + be.x;
        o.y = (v.y * inv - mean.y) * scale.y + be.y;
        o.z = (v.z * inv - mean.z) * scale.z + be.z;
        o.w = (v.w * inv - mean.w) * scale.w + be.w;
        o4[(size_t)r * 32 + c4] = o;
        gs[(size_t)r * 32 + c4] = z4;   // restore zeros for next launch/replay
    }
}

extern "C" void kernel_launch(void* const* d_in, const int* in_sizes, int n_in,
                              void* d_out, int out_size)
{
    const float* x     = (const float*)d_in[0];
    const float* W     = (const float*)d_in[1];
    const float* bvec  = (const float*)d_in[2];
    const float* gamma = (const float*)d_in[3];
    const float* beta  = (const float*)d_in[4];
    const int*   seg   = (const int*)d_in[5];
    const int*   blen  = (const int*)d_in[6];
    float*       out   = (float*)d_out;

    (void)in_sizes; (void)n_in; (void)out_size;

    void* scratch = nullptr;
    cudaGetSymbolAddress(&scratch, g_scratch);
    cudaMemsetAsync((char*)scratch + sizeof(float) * (size_t)N_BAGS_K * BAG_K, 0,
                    sizeof(float) * 2 * BAG_K, 0);

    int dev = 0, nsm = 148;
    cudaGetDevice(&dev);
    cudaDeviceGetAttribute(&nsm, cudaDevAttrMultiProcessorCount, dev);

    cudaFuncSetAttribute(fused_gemm_seg_kernel,
                         cudaFuncAttributeMaxDynamicSharedMemorySize, SMEM_DYN);
    fused_gemm_seg_kernel<<<nsm, 512, SMEM_DYN>>>(x, W, bvec, seg);
    stats_kernel<<<256, 256>>>(blen);
    norm_kernel<<<1024, 256>>>(blen, gamma, beta, out);
}